// round 14
// baseline (speedup 1.0000x reference)
#include <cuda_runtime.h>
#include <cuda_fp16.h>
#include <cstdint>

#define NN 10000
#define NE 50000
#define WD 64
#define DEPTH 4
#define KP2 4224          // 4096 (P) + 64 (S/bias) + 64 (h/root)
#define NROWS 10112       // 632 tiles * 16 rows
#define NTILES 632
#define KFPT 264          // KP2/16 fragment-groups per tile
#define TILE_U32 (KFPT * 128)
#define MAXDEG 32
#define KSPLIT 6
#define KQ 704            // KP2 / 6
#define KSTEP 64
#define KSTEPS 11         // KQ / 64

typedef unsigned long long u64;

// ================= mma.sync / ldmatrix helpers ==============================
__device__ __forceinline__ uint32_t s2u(const void* p) {
    uint32_t a;
    asm("{ .reg .u64 t; cvta.to.shared.u64 t, %1; cvt.u32.u64 %0, t; }" : "=r"(a) : "l"(p));
    return a;
}
__device__ __forceinline__ void ldsm4(uint32_t* r, uint32_t addr) {
    asm volatile("ldmatrix.sync.aligned.m8n8.x4.shared.b16 {%0,%1,%2,%3}, [%4];"
        : "=r"(r[0]), "=r"(r[1]), "=r"(r[2]), "=r"(r[3]) : "r"(addr));
}
__device__ __forceinline__ void mma16816(float* c, const uint32_t* a, const uint32_t* b) {
    asm volatile(
        "mma.sync.aligned.m16n8k16.row.col.f32.f16.f16.f32 "
        "{%0,%1,%2,%3}, {%4,%5,%6,%7}, {%8,%9}, {%0,%1,%2,%3};"
        : "+f"(c[0]), "+f"(c[1]), "+f"(c[2]), "+f"(c[3])
        : "r"(a[0]), "r"(a[1]), "r"(a[2]), "r"(a[3]), "r"(b[0]), "r"(b[1]));
}

// ================= scratch =================================================
__device__ uint32_t g_Af[(size_t)NTILES * TILE_U32];  // 85.4 MB A in FRAGMENT layout
__device__ __half g_B[WD * KP2];               // B^T [o][k] single fp16, 528 KB
__device__ float g_agg[NN * WD];               // atomic accumulator (2.5 MB)
__device__ float g_t[NE * WD];                 // relu(ea@k1+b1), edge order
__device__ float g_h[2][NN * WD];
__device__ int   g_fill[NN];                   // becomes in-degree after k_en
__device__ int   g_es_src[NN * MAXDEG];        // padded CSR: src per slot
__device__ int   g_es_eid[NN * MAXDEG];        // padded CSR: edge id per slot

// Write 4 consecutive A-cols (C 4-aligned) of row r into fragment layout.
// u32 = {half(C), half(C+1)}: slot reg=(r>>3)|((p>>2)<<1), lane=(r&7)*4+(p&3),
// p=(C>>1)&7; second u32 (C+2,C+3) lands at lane+1, same reg.
__device__ __forceinline__ void frag_store4(uint32_t* Af, int r, int C,
                                            float v0, float v1, float v2, float v3) {
    __half2 h01 = __floats2half2_rn(v0, v1);
    __half2 h23 = __floats2half2_rn(v2, v3);
    int kf = C >> 4;
    int p0 = (C >> 1) & 7;
    int reg0 = (r >> 3) | ((p0 >> 2) << 1);
    int l0 = (r & 7) * 4 + (p0 & 3);
    Af[kf * 128 + l0 * 4 + reg0] = *(uint32_t*)&h01;
    Af[kf * 128 + (l0 + 1) * 4 + reg0] = *(uint32_t*)&h23;
}

// ================= setup kernels ===========================================
// fused: edge MLP + padded-CSR scatter + node MLP
__global__ void k_en(const float* __restrict__ ea, const int* __restrict__ ei,
                     const float* __restrict__ k1W, const float* __restrict__ k1b,
                     const float* __restrict__ x, const float* __restrict__ W1,
                     const float* __restrict__ b1) {
    int i = blockIdx.x * 256 + threadIdx.x;
    if (i < NE * WD) {
        int e = i >> 6, o = i & 63;
        float a0 = ea[e * 3 + 0], a1 = ea[e * 3 + 1], a2 = ea[e * 3 + 2];
        float t = fmaf(a0, k1W[o], fmaf(a1, k1W[64 + o], fmaf(a2, k1W[128 + o], k1b[o])));
        g_t[i] = t > 0.f ? t : 0.f;
        if (o == 0) {
            int dst = ei[NE + e];
            int pos = atomicAdd(&g_fill[dst], 1);
            if (pos < MAXDEG) {
                g_es_src[dst * MAXDEG + pos] = ei[e];
                g_es_eid[dst * MAXDEG + pos] = e;
            }
        }
    } else if (i < NE * WD + NN * WD) {
        int j = i - NE * WD;
        int n = j >> 6, o = j & 63;
        float v = fmaf(x[n * 3 + 0], W1[o],
                  fmaf(x[n * 3 + 1], W1[64 + o],
                  fmaf(x[n * 3 + 2], W1[128 + o], b1[o])));
        g_h[0][j] = v;
    }
}

// fused: B^T permute (single fp16) AND zero-pad A tiles 625..631 (all-pad rows)
__global__ void k_prep(const float* __restrict__ k2W, const float* __restrict__ k2b,
                       const float* __restrict__ root) {
    int j = blockIdx.x * 256 + threadIdx.x;
    if (j < WD * KP2) {
        int o = j / KP2, k = j % KP2;
        float v;
        if (k < 4096) {
            int i = k >> 6, kq = k & 63;
            v = k2W[kq * 4096 + i * 64 + o];
        } else if (k < 4160) {
            v = k2b[(k - 4096) * 64 + o];
        } else {
            v = root[(k - 4160) * 64 + o];
        }
        g_B[j] = __float2half_rn(v);
    } else {
        int p = j - WD * KP2;
        if (p < 7 * TILE_U32) g_Af[(size_t)625 * TILE_U32 + p] = 0u;
    }
}

// ================= per-iteration kernels ===================================
// A row n = [ invd*(sum_e h_src ⊗ t_e) | invd*(sum_e h_src) | h_n ], fp16,
// written directly in mma fragment layout.
__global__ void k_build(int cur) {
    __shared__ float sh[16][128];
    int n = blockIdx.x;
    int tid = threadIdx.x;
    int deg = g_fill[n];
    if (deg > MAXDEG) deg = MAXDEG;
    int ti = tid >> 4, tk = tid & 15;
    float acc[16];
#pragma unroll
    for (int p = 0; p < 16; p++) acc[p] = 0.f;
    float4 sacc = make_float4(0.f, 0.f, 0.f, 0.f);
    const float* __restrict__ h = g_h[cur];
    int ebase = n * MAXDEG;
    for (int base = 0; base < deg; base += 16) {
        int nb = min(16, deg - base);
        __syncthreads();
        for (int idx = tid; idx < nb * 128; idx += 256) {
            int j = idx >> 7, f = idx & 127;
            int sl = ebase + base + j;
            if (f < 64) sh[j][f] = h[g_es_src[sl] * 64 + f];
            else        sh[j][f] = g_t[g_es_eid[sl] * 64 + f - 64];
        }
        __syncthreads();
        for (int j = 0; j < nb; j++) {
            float4 hq = *(const float4*)&sh[j][ti * 4];
            float4 tq = *(const float4*)&sh[j][64 + tk * 4];
            acc[0]  = fmaf(hq.x, tq.x, acc[0]);  acc[1]  = fmaf(hq.x, tq.y, acc[1]);
            acc[2]  = fmaf(hq.x, tq.z, acc[2]);  acc[3]  = fmaf(hq.x, tq.w, acc[3]);
            acc[4]  = fmaf(hq.y, tq.x, acc[4]);  acc[5]  = fmaf(hq.y, tq.y, acc[5]);
            acc[6]  = fmaf(hq.y, tq.z, acc[6]);  acc[7]  = fmaf(hq.y, tq.w, acc[7]);
            acc[8]  = fmaf(hq.z, tq.x, acc[8]);  acc[9]  = fmaf(hq.z, tq.y, acc[9]);
            acc[10] = fmaf(hq.z, tq.z, acc[10]); acc[11] = fmaf(hq.z, tq.w, acc[11]);
            acc[12] = fmaf(hq.w, tq.x, acc[12]); acc[13] = fmaf(hq.w, tq.y, acc[13]);
            acc[14] = fmaf(hq.w, tq.z, acc[14]); acc[15] = fmaf(hq.w, tq.w, acc[15]);
            if (tk == 0) {
                sacc.x += hq.x; sacc.y += hq.y; sacc.z += hq.z; sacc.w += hq.w;
            }
        }
    }
    float inv = 1.0f / (float)(deg > 0 ? deg : 1);
    uint32_t* Af = g_Af + (size_t)(n >> 4) * TILE_U32;
    int r = n & 15;
#pragma unroll
    for (int di = 0; di < 4; di++)
        frag_store4(Af, r, (ti * 4 + di) * 64 + tk * 4,
                    acc[di * 4 + 0] * inv, acc[di * 4 + 1] * inv,
                    acc[di * 4 + 2] * inv, acc[di * 4 + 3] * inv);
    if (tk == 0) {
        frag_store4(Af, r, 4096 + ti * 4,
                    sacc.x * inv, sacc.y * inv, sacc.z * inv, sacc.w * inv);
        float4 hq = *(const float4*)&h[n * 64 + ti * 4];
        frag_store4(Af, r, 4160 + ti * 4, hq.x, hq.y, hq.z, hq.w);
    }
}

// mma.sync fp16 GEMM, fragment-direct A:
// block M=64 x N=64, 256 thr = 8 warps of m16n32 (4 M x 2 N).
// A fragments loaded as one LDG.128/kf/warp straight from g_Af (no smem, no ldsm).
// B staged in smem with register prefetch. Epilogue: atomicAdd into g_agg.
#define PITCH 72                  // fp16 elems per smem row (64 + 8 pad = 144 B)
__global__ void __launch_bounds__(256) k_gemm() {
    __shared__ __half sB[64 * PITCH];

    int tid = threadIdx.x;
    int warp = tid >> 5, lane = tid & 31;
    int n0 = blockIdx.x * 64;
    int ks = blockIdx.y;
    int mt = warp >> 1;                 // m16 tile in block (0..3)
    int wn = (warp & 1) * 32;           // N offset 0 or 32

    const uint32_t* Ab = g_Af + (size_t)((n0 >> 4) + mt) * TILE_U32 + lane * 4;
    uint32_t uB = s2u(sB);

    float c[4][4];
#pragma unroll
    for (int f = 0; f < 4; f++)
#pragma unroll
        for (int qq = 0; qq < 4; qq++) c[f][qq] = 0.f;

    uint32_t boffB = (uint32_t)(wn + (lane & 7) + ((lane >> 4) & 1) * 8) * (PITCH * 2)
                   + (((lane >> 3) & 1) * 16);

    // B loader: 512 uint4 per step / 256 threads -> 2 each
    int lr = tid >> 3, lu = tid & 7;
    int lr2 = (tid + 256) >> 3, lu2 = (tid + 256) & 7;
    uint32_t sBo1 = (uint32_t)lr * PITCH + lu * 8;
    uint32_t sBo2 = (uint32_t)lr2 * PITCH + lu2 * 8;

    int kb = ks * KQ;
    uint4 pb0 = *(const uint4*)(g_B + (size_t)lr * KP2 + kb + lu * 8);
    uint4 pb1 = *(const uint4*)(g_B + (size_t)lr2 * KP2 + kb + lu2 * 8);

    for (int step = 0; step < KSTEPS; step++) {
        __syncthreads();
        *(uint4*)(sB + sBo1) = pb0;
        *(uint4*)(sB + sBo2) = pb1;
        __syncthreads();

        if (step + 1 < KSTEPS) {
            int kn = kb + KSTEP;
            pb0 = *(const uint4*)(g_B + (size_t)lr * KP2 + kn + lu * 8);
            pb1 = *(const uint4*)(g_B + (size_t)lr2 * KP2 + kn + lu2 * 8);
        }

        int kf0 = kb >> 4;
#pragma unroll
        for (int kf = 0; kf < 4; kf++) {
            uint4 av = *(const uint4*)(Ab + (size_t)(kf0 + kf) * 128);
            uint32_t* a = (uint32_t*)&av;
            uint32_t koff = kf * 32;
#pragma unroll
            for (int ng = 0; ng < 2; ng++) {
                uint32_t b[4];
                ldsm4(b, uB + boffB + (uint32_t)(ng * 16) * (PITCH * 2) + koff);
                mma16816(c[ng * 2 + 0], a, b + 0);
                mma16816(c[ng * 2 + 1], a, b + 2);
            }
        }
        kb += KSTEP;
    }

#pragma unroll
    for (int f = 0; f < 4; f++) {
        int ng = f >> 1, half = f & 1;
        int col = wn + ng * 16 + half * 8 + (lane & 3) * 2;
        int r0 = n0 + mt * 16 + (lane >> 2);
        if (r0 < NN) {
            atomicAdd(&g_agg[r0 * 64 + col], c[f][0]);
            atomicAdd(&g_agg[r0 * 64 + col + 1], c[f][1]);
        }
        int r1 = r0 + 8;
        if (r1 < NN) {
            atomicAdd(&g_agg[r1 * 64 + col], c[f][2]);
            atomicAdd(&g_agg[r1 * 64 + col + 1], c[f][3]);
        }
    }
}

// h' = relu(agg + conv_b); re-zero agg for the next iteration
__global__ void k_comb(const float* __restrict__ cb, int nxt) {
    int i = blockIdx.x * 256 + threadIdx.x;
    if (i >= NN * 64) return;
    float v = g_agg[i] + cb[i & 63];
    g_agg[i] = 0.f;
    g_h[nxt][i] = v > 0.f ? v : 0.f;
}

__global__ void k_out(const float* __restrict__ w2, const float* __restrict__ b2,
                      float* __restrict__ out, int cur) {
    int warp = threadIdx.x >> 5, lane = threadIdx.x & 31;
    int n = blockIdx.x * 8 + warp;
    if (n >= NN) return;
    const float* h = g_h[cur] + n * 64;
    float s = h[lane] * w2[lane] + h[32 + lane] * w2[32 + lane];
#pragma unroll
    for (int d = 16; d; d >>= 1) s += __shfl_xor_sync(0xffffffff, s, d);
    if (lane == 0) out[n] = s + b2[0];
}

// ================= launch ==================================================
extern "C" void kernel_launch(void* const* d_in, const int* in_sizes, int n_in,
                              void* d_out, int out_size) {
    const float* x    = (const float*)d_in[0];
    const int*   ei   = (const int*)  d_in[1];
    const float* ea   = (const float*)d_in[2];
    const float* fc1W = (const float*)d_in[3];
    const float* fc1b = (const float*)d_in[4];
    const float* k1W  = (const float*)d_in[5];
    const float* k1b  = (const float*)d_in[6];
    const float* k2W  = (const float*)d_in[7];
    const float* k2b  = (const float*)d_in[8];
    const float* root = (const float*)d_in[9];
    const float* cb   = (const float*)d_in[10];
    const float* fc2W = (const float*)d_in[11];
    const float* fc2b = (const float*)d_in[12];
    float* out = (float*)d_out;

    void* p_fill = nullptr; void* p_agg = nullptr;
    cudaGetSymbolAddress(&p_fill, g_fill);
    cudaGetSymbolAddress(&p_agg, g_agg);
    cudaMemsetAsync(p_fill, 0, NN * sizeof(int));
    cudaMemsetAsync(p_agg, 0, NN * WD * sizeof(float));

    const int prep_threads = WD * KP2 + 7 * TILE_U32;
    dim3 gg(NROWS / 64, KSPLIT);
    int cur = 0;

    // launch index:  0=k_en  1=k_build  2=k_prep  3=k_gemm (ncu capture slot)
    k_en<<<((NE + NN) * WD + 255) / 256, 256>>>(ea, ei, k1W, k1b, x, fc1W, fc1b);
    for (int d = 0; d < DEPTH; d++) {
        k_build<<<NN, 256>>>(cur);
        if (d == 0) k_prep<<<(prep_threads + 255) / 256, 256>>>(k2W, k2b, root);
        k_gemm<<<gg, 256>>>();
        k_comb<<<(NN * 64 + 255) / 256, 256>>>(cb, cur ^ 1);
        cur ^= 1;
    }
    k_out<<<(NN + 7) / 8, 256>>>(fc2W, fc2b, out, cur);
}

// round 15
// speedup vs baseline: 1.3641x; 1.3641x over previous
#include <cuda_runtime.h>
#include <cuda_fp16.h>
#include <cstdint>

#define NN 10000
#define NE 50000
#define WD 64
#define DEPTH 4
#define KP2 4224          // 4096 (P) + 64 (S/bias) + 64 (h/root)
#define NROWS 10112       // 158 * 64, padded
#define MAXDEG 32
#define KSPLIT 6
#define KQ 704            // KP2 / 6
#define KSTEP 64
#define KSTEPS 11         // KQ / 64

typedef unsigned long long u64;

// ================= mma.sync / ldmatrix helpers ==============================
__device__ __forceinline__ uint32_t s2u(const void* p) {
    uint32_t a;
    asm("{ .reg .u64 t; cvta.to.shared.u64 t, %1; cvt.u32.u64 %0, t; }" : "=r"(a) : "l"(p));
    return a;
}
__device__ __forceinline__ void ldsm4(uint32_t* r, uint32_t addr) {
    asm volatile("ldmatrix.sync.aligned.m8n8.x4.shared.b16 {%0,%1,%2,%3}, [%4];"
        : "=r"(r[0]), "=r"(r[1]), "=r"(r[2]), "=r"(r[3]) : "r"(addr));
}
__device__ __forceinline__ void mma16816(float* c, const uint32_t* a, const uint32_t* b) {
    asm volatile(
        "mma.sync.aligned.m16n8k16.row.col.f32.f16.f16.f32 "
        "{%0,%1,%2,%3}, {%4,%5,%6,%7}, {%8,%9}, {%0,%1,%2,%3};"
        : "+f"(c[0]), "+f"(c[1]), "+f"(c[2]), "+f"(c[3])
        : "r"(a[0]), "r"(a[1]), "r"(a[2]), "r"(a[3]), "r"(b[0]), "r"(b[1]));
}

// ================= scratch =================================================
__device__ __half g_A[(size_t)NROWS * KP2];    // 85.4 MB single-fp16 A
__device__ __half g_B[WD * KP2];               // B^T [o][k] single fp16, 528 KB
__device__ float g_aggp[KSPLIT * NN * WD];     // K-split partials
__device__ uint32_t g_t16[NE * 32];            // relu(ea@k1+b1), packed half2
__device__ float g_h[2][NN * WD];
__device__ int   g_fill[NN];                   // becomes in-degree after k_en
__device__ int   g_es_src[NN * MAXDEG];        // padded CSR: src per slot
__device__ int   g_es_eid[NN * MAXDEG];        // padded CSR: edge id per slot

// ================= setup kernels ===========================================
// fused: edge MLP (2 outputs/thread, packed fp16) + padded-CSR scatter + node MLP
__global__ void k_en(const float* __restrict__ ea, const int* __restrict__ ei,
                     const float* __restrict__ k1W, const float* __restrict__ k1b,
                     const float* __restrict__ x, const float* __restrict__ W1,
                     const float* __restrict__ b1) {
    int i = blockIdx.x * 256 + threadIdx.x;
    if (i < NE * 32) {
        int e = i >> 5, q = i & 31;
        int o0 = 2 * q, o1 = 2 * q + 1;
        float a0 = ea[e * 3 + 0], a1 = ea[e * 3 + 1], a2 = ea[e * 3 + 2];
        float t0 = fmaf(a0, k1W[o0], fmaf(a1, k1W[64 + o0], fmaf(a2, k1W[128 + o0], k1b[o0])));
        float t1 = fmaf(a0, k1W[o1], fmaf(a1, k1W[64 + o1], fmaf(a2, k1W[128 + o1], k1b[o1])));
        __half2 tp = __floats2half2_rn(t0 > 0.f ? t0 : 0.f, t1 > 0.f ? t1 : 0.f);
        g_t16[i] = *(uint32_t*)&tp;
        if (q == 0) {
            int dst = ei[NE + e];
            int pos = atomicAdd(&g_fill[dst], 1);
            if (pos < MAXDEG) {
                g_es_src[dst * MAXDEG + pos] = ei[e];
                g_es_eid[dst * MAXDEG + pos] = e;
            }
        }
    } else if (i < NE * 32 + NN * WD) {
        int j = i - NE * 32;
        int n = j >> 6, o = j & 63;
        float v = fmaf(x[n * 3 + 0], W1[o],
                  fmaf(x[n * 3 + 1], W1[64 + o],
                  fmaf(x[n * 3 + 2], W1[128 + o], b1[o])));
        g_h[0][j] = v;
    }
}

// fused: B^T permute (single fp16) AND zero-pad A rows NN..NROWS
__global__ void k_prep(const float* __restrict__ k2W, const float* __restrict__ k2b,
                       const float* __restrict__ root) {
    int j = blockIdx.x * 256 + threadIdx.x;
    if (j < WD * KP2) {
        int o = j / KP2, k = j % KP2;
        float v;
        if (k < 4096) {
            int i = k >> 6, kq = k & 63;
            v = k2W[kq * 4096 + i * 64 + o];
        } else if (k < 4160) {
            v = k2b[(k - 4096) * 64 + o];
        } else {
            v = root[(k - 4160) * 64 + o];
        }
        g_B[j] = __float2half_rn(v);
    } else {
        int p = j - WD * KP2;
        if (p < (NROWS - NN) * KP2) g_A[(size_t)NN * KP2 + p] = __float2half_rn(0.f);
    }
}

// ================= per-iteration kernels ===================================
// A row n = [ invd*(sum_e h_src ⊗ t_e) | invd*(sum_e h_src) | h_n ], fp16.
// h in smem fp32 (broadcast reads), t in smem fp16 (distinct reads, half bytes).
__global__ void k_build(int cur) {
    __shared__ float sh_h[16][64];
    __shared__ uint32_t sh_t[16][32];
    int n = blockIdx.x;
    int tid = threadIdx.x;
    int deg = g_fill[n];
    if (deg > MAXDEG) deg = MAXDEG;
    int ti = tid >> 4, tk = tid & 15;
    float acc[16];
#pragma unroll
    for (int p = 0; p < 16; p++) acc[p] = 0.f;
    float4 sacc = make_float4(0.f, 0.f, 0.f, 0.f);
    const float* __restrict__ h = g_h[cur];
    int ebase = n * MAXDEG;
    for (int base = 0; base < deg; base += 16) {
        int nb = min(16, deg - base);
        __syncthreads();
        for (int idx = tid; idx < nb * 64; idx += 256) {
            int j = idx >> 6, f = idx & 63;
            sh_h[j][f] = h[g_es_src[ebase + base + j] * 64 + f];
        }
        for (int idx = tid; idx < nb * 32; idx += 256) {
            int j = idx >> 5, f = idx & 31;
            sh_t[j][f] = g_t16[g_es_eid[ebase + base + j] * 32 + f];
        }
        __syncthreads();
        for (int j = 0; j < nb; j++) {
            float4 hq = *(const float4*)&sh_h[j][ti * 4];
            uint2 tv = *(const uint2*)&sh_t[j][tk * 2];
            float2 tlo = __half22float2(*(__half2*)&tv.x);
            float2 thi = __half22float2(*(__half2*)&tv.y);
            acc[0]  = fmaf(hq.x, tlo.x, acc[0]);  acc[1]  = fmaf(hq.x, tlo.y, acc[1]);
            acc[2]  = fmaf(hq.x, thi.x, acc[2]);  acc[3]  = fmaf(hq.x, thi.y, acc[3]);
            acc[4]  = fmaf(hq.y, tlo.x, acc[4]);  acc[5]  = fmaf(hq.y, tlo.y, acc[5]);
            acc[6]  = fmaf(hq.y, thi.x, acc[6]);  acc[7]  = fmaf(hq.y, thi.y, acc[7]);
            acc[8]  = fmaf(hq.z, tlo.x, acc[8]);  acc[9]  = fmaf(hq.z, tlo.y, acc[9]);
            acc[10] = fmaf(hq.z, thi.x, acc[10]); acc[11] = fmaf(hq.z, thi.y, acc[11]);
            acc[12] = fmaf(hq.w, tlo.x, acc[12]); acc[13] = fmaf(hq.w, tlo.y, acc[13]);
            acc[14] = fmaf(hq.w, thi.x, acc[14]); acc[15] = fmaf(hq.w, thi.y, acc[15]);
            if (tk == 0) {
                sacc.x += hq.x; sacc.y += hq.y; sacc.z += hq.z; sacc.w += hq.w;
            }
        }
    }
    float inv = 1.0f / (float)(deg > 0 ? deg : 1);
    size_t rowo = (size_t)n * KP2;
#pragma unroll
    for (int di = 0; di < 4; di++) {
        __half2 p0 = __floats2half2_rn(acc[di * 4 + 0] * inv, acc[di * 4 + 1] * inv);
        __half2 p1 = __floats2half2_rn(acc[di * 4 + 2] * inv, acc[di * 4 + 3] * inv);
        uint2 v;
        v.x = *(uint32_t*)&p0;
        v.y = *(uint32_t*)&p1;
        *(uint2*)(g_A + rowo + (ti * 4 + di) * 64 + tk * 4) = v;
    }
    if (tk == 0) {
        __half2 s0 = __floats2half2_rn(sacc.x * inv, sacc.y * inv);
        __half2 s1 = __floats2half2_rn(sacc.z * inv, sacc.w * inv);
        uint2 v;
        v.x = *(uint32_t*)&s0;
        v.y = *(uint32_t*)&s1;
        *(uint2*)(g_A + rowo + 4096 + ti * 4) = v;
        float4 hq = *(const float4*)&h[n * 64 + ti * 4];
        __half2 h0 = __floats2half2_rn(hq.x, hq.y);
        __half2 h1 = __floats2half2_rn(hq.z, hq.w);
        v.x = *(uint32_t*)&h0;
        v.y = *(uint32_t*)&h1;
        *(uint2*)(g_A + rowo + 4160 + ti * 4) = v;
    }
}

// mma.sync fp16 GEMM, DOUBLE-BUFFERED smem (1 barrier/step):
// block M=64 x N=64, 256 thr = 8 warps of m16n32 (4 M x 2 N).
// grid 158 x 6 = 948 blocks, 11 k64-steps.
#define PITCH 72                  // fp16 elems per smem row (64 + 8 pad = 144 B)
__global__ void __launch_bounds__(256) k_gemm() {
    __shared__ __half sA[2][64 * PITCH];
    __shared__ __half sB[2][64 * PITCH];

    int tid = threadIdx.x;
    int warp = tid >> 5, lane = tid & 31;
    int n0 = blockIdx.x * 64;
    int ks = blockIdx.y;
    int wm = (warp >> 1) * 16;          // M offset 0..48
    int wn = (warp & 1) * 32;           // N offset 0 or 32

    uint32_t uA0 = s2u(sA[0]), uA1 = s2u(sA[1]);
    uint32_t uB0 = s2u(sB[0]), uB1 = s2u(sB[1]);

    float c[4][4];
#pragma unroll
    for (int f = 0; f < 4; f++)
#pragma unroll
        for (int qq = 0; qq < 4; qq++) c[f][qq] = 0.f;

    uint32_t aoff = (uint32_t)(wm + (lane & 15)) * (PITCH * 2) + ((lane >> 4) * 16);
    uint32_t boffB = (uint32_t)(wn + (lane & 7) + ((lane >> 4) & 1) * 8) * (PITCH * 2)
                   + (((lane >> 3) & 1) * 16);

    // loaders: 512 uint4 per array per step / 256 threads -> 2 each
    int lr = tid >> 3, lu = tid & 7;
    int lr2 = (tid + 256) >> 3, lu2 = (tid + 256) & 7;
    uint32_t so1 = (uint32_t)lr * PITCH + lu * 8;
    uint32_t so2 = (uint32_t)lr2 * PITCH + lu2 * 8;

    int kb = ks * KQ;
    uint4 pa0, pa1, pb0, pb1;
    // stage 0 direct
    pa0 = *(const uint4*)(g_A + (size_t)(n0 + lr) * KP2 + kb + lu * 8);
    pa1 = *(const uint4*)(g_A + (size_t)(n0 + lr2) * KP2 + kb + lu2 * 8);
    pb0 = *(const uint4*)(g_B + (size_t)lr * KP2 + kb + lu * 8);
    pb1 = *(const uint4*)(g_B + (size_t)lr2 * KP2 + kb + lu2 * 8);
    *(uint4*)(sA[0] + so1) = pa0;
    *(uint4*)(sA[0] + so2) = pa1;
    *(uint4*)(sB[0] + so1) = pb0;
    *(uint4*)(sB[0] + so2) = pb1;
    // prefetch stage 1 into regs
    {
        int kn = kb + KSTEP;
        pa0 = *(const uint4*)(g_A + (size_t)(n0 + lr) * KP2 + kn + lu * 8);
        pa1 = *(const uint4*)(g_A + (size_t)(n0 + lr2) * KP2 + kn + lu2 * 8);
        pb0 = *(const uint4*)(g_B + (size_t)lr * KP2 + kn + lu * 8);
        pb1 = *(const uint4*)(g_B + (size_t)lr2 * KP2 + kn + lu2 * 8);
    }
    __syncthreads();

    for (int step = 0; step < KSTEPS; step++) {
        // fill next buffer while computing current (different buffers, no race)
        if (step + 1 < KSTEPS) {
            __half* dA = (step + 1) & 1 ? sA[1] : sA[0];
            __half* dB = (step + 1) & 1 ? sB[1] : sB[0];
            *(uint4*)(dA + so1) = pa0;
            *(uint4*)(dA + so2) = pa1;
            *(uint4*)(dB + so1) = pb0;
            *(uint4*)(dB + so2) = pb1;
            if (step + 2 < KSTEPS) {
                int kn = kb + 2 * KSTEP;
                pa0 = *(const uint4*)(g_A + (size_t)(n0 + lr) * KP2 + kn + lu * 8);
                pa1 = *(const uint4*)(g_A + (size_t)(n0 + lr2) * KP2 + kn + lu2 * 8);
                pb0 = *(const uint4*)(g_B + (size_t)lr * KP2 + kn + lu * 8);
                pb1 = *(const uint4*)(g_B + (size_t)lr2 * KP2 + kn + lu2 * 8);
            }
        }

        uint32_t cA = (step & 1) ? uA1 : uA0;
        uint32_t cB = (step & 1) ? uB1 : uB0;
#pragma unroll
        for (int kf = 0; kf < 4; kf++) {
            uint32_t koff = kf * 32;   // 16 fp16 = 32 B
            uint32_t a[4];
            ldsm4(a, cA + aoff + koff);
#pragma unroll
            for (int ng = 0; ng < 2; ng++) {
                uint32_t b[4];
                ldsm4(b, cB + boffB + (uint32_t)(ng * 16) * (PITCH * 2) + koff);
                mma16816(c[ng * 2 + 0], a, b + 0);
                mma16816(c[ng * 2 + 1], a, b + 2);
            }
        }
        kb += KSTEP;
        __syncthreads();
    }

    float* outp = g_aggp + (size_t)ks * NN * 64;
#pragma unroll
    for (int f = 0; f < 4; f++) {
        int ng = f >> 1, half = f & 1;
        int col = wn + ng * 16 + half * 8 + (lane & 3) * 2;
        int r0 = n0 + wm + (lane >> 2);
        if (r0 < NN) *(float2*)(outp + r0 * 64 + col) = make_float2(c[f][0], c[f][1]);
        int r1 = r0 + 8;
        if (r1 < NN) *(float2*)(outp + r1 * 64 + col) = make_float2(c[f][2], c[f][3]);
    }
}

// h' = relu(sum of 6 partials + conv_b)
__global__ void k_comb(const float* __restrict__ cb, int nxt) {
    int i = blockIdx.x * 256 + threadIdx.x;
    if (i >= NN * 64) return;
    int o = i & 63;
    float v = cb[o];
#pragma unroll
    for (int s = 0; s < KSPLIT; s++) v += g_aggp[(size_t)s * NN * 64 + i];
    g_h[nxt][i] = v > 0.f ? v : 0.f;
}

__global__ void k_out(const float* __restrict__ w2, const float* __restrict__ b2,
                      float* __restrict__ out, int cur) {
    int warp = threadIdx.x >> 5, lane = threadIdx.x & 31;
    int n = blockIdx.x * 8 + warp;
    if (n >= NN) return;
    const float* h = g_h[cur] + n * 64;
    float s = h[lane] * w2[lane] + h[32 + lane] * w2[32 + lane];
#pragma unroll
    for (int d = 16; d; d >>= 1) s += __shfl_xor_sync(0xffffffff, s, d);
    if (lane == 0) out[n] = s + b2[0];
}

// ================= launch ==================================================
extern "C" void kernel_launch(void* const* d_in, const int* in_sizes, int n_in,
                              void* d_out, int out_size) {
    const float* x    = (const float*)d_in[0];
    const int*   ei   = (const int*)  d_in[1];
    const float* ea   = (const float*)d_in[2];
    const float* fc1W = (const float*)d_in[3];
    const float* fc1b = (const float*)d_in[4];
    const float* k1W  = (const float*)d_in[5];
    const float* k1b  = (const float*)d_in[6];
    const float* k2W  = (const float*)d_in[7];
    const float* k2b  = (const float*)d_in[8];
    const float* root = (const float*)d_in[9];
    const float* cb   = (const float*)d_in[10];
    const float* fc2W = (const float*)d_in[11];
    const float* fc2b = (const float*)d_in[12];
    float* out = (float*)d_out;

    void* p_fill = nullptr;
    cudaGetSymbolAddress(&p_fill, g_fill);
    cudaMemsetAsync(p_fill, 0, NN * sizeof(int));

    const int prep_threads = WD * KP2 + (NROWS - NN) * KP2;
    dim3 gg(NROWS / 64, KSPLIT);
    int cur = 0;

    // launch index:  0=k_en  1=k_build  2=k_prep  3=k_gemm (ncu capture slot)
    k_en<<<((NE * 32 + NN * WD) + 255) / 256, 256>>>(ea, ei, k1W, k1b, x, fc1W, fc1b);
    for (int d = 0; d < DEPTH; d++) {
        k_build<<<NN, 256>>>(cur);
        if (d == 0) k_prep<<<(prep_threads + 255) / 256, 256>>>(k2W, k2b, root);
        k_gemm<<<gg, 256>>>();
        k_comb<<<(NN * 64 + 255) / 256, 256>>>(cb, cur ^ 1);
        cur ^= 1;
    }
    k_out<<<(NN + 7) / 8, 256>>>(fc2W, fc2b, out, cur);
}